// round 11
// baseline (speedup 1.0000x reference)
#include <cuda_runtime.h>
#include <cuda_bf16.h>
#include <cstdint>

#define NHEADS 16
#define HDIM   64
#define BATCH  2
#define SEQ    2048
#define DM     1024
#define MT     (BATCH*SEQ)   // 4096

// ---------------- scratch (device globals; allocation-free) ----------------
__device__ __nv_bfloat16 g_xh[(size_t)MT*DM],   g_xl[(size_t)MT*DM];
__device__ __nv_bfloat16 g_wh[(size_t)3*DM*DM], g_wl[(size_t)3*DM*DM];
__device__ __nv_bfloat16 g_oh[(size_t)DM*DM],   g_ol[(size_t)DM*DM];
__device__ __nv_bfloat16 g_ah[(size_t)MT*DM],   g_al[(size_t)MT*DM];
__device__ __nv_bfloat16 g_qh[(size_t)BATCH*NHEADS*SEQ*HDIM], g_ql[(size_t)BATCH*NHEADS*SEQ*HDIM];
__device__ __nv_bfloat16 g_kh[(size_t)BATCH*NHEADS*SEQ*HDIM], g_kl[(size_t)BATCH*NHEADS*SEQ*HDIM];
__device__ __nv_bfloat16 g_vh[(size_t)BATCH*NHEADS*SEQ*HDIM], g_vl[(size_t)BATCH*NHEADS*SEQ*HDIM];

// ---------------- helpers ----------------
__device__ __forceinline__ uint32_t smem_u32(const void* p) {
    uint32_t a;
    asm("{ .reg .u64 t; cvta.to.shared.u64 t, %1; cvt.u32.u64 %0, t; }" : "=r"(a) : "l"(p));
    return a;
}
__device__ __forceinline__ void cp_async16(uint32_t dst, const void* src) {
    asm volatile("cp.async.cg.shared.global [%0], [%1], 16;" :: "r"(dst), "l"(src));
}
#define CP_COMMIT()  asm volatile("cp.async.commit_group;" ::: "memory")
#define CP_WAIT1()   asm volatile("cp.async.wait_group 1;" ::: "memory")
#define CP_WAIT0()   asm volatile("cp.async.wait_group 0;" ::: "memory")

__device__ __forceinline__ void ldsm_x4(uint32_t& r0, uint32_t& r1, uint32_t& r2, uint32_t& r3, uint32_t a) {
    asm volatile("ldmatrix.sync.aligned.m8n8.x4.shared.b16 {%0,%1,%2,%3}, [%4];"
        : "=r"(r0), "=r"(r1), "=r"(r2), "=r"(r3) : "r"(a));
}
__device__ __forceinline__ void ldsm_x2(uint32_t& r0, uint32_t& r1, uint32_t a) {
    asm volatile("ldmatrix.sync.aligned.m8n8.x2.shared.b16 {%0,%1}, [%2];"
        : "=r"(r0), "=r"(r1) : "r"(a));
}
__device__ __forceinline__ void ldsm_x2t(uint32_t& r0, uint32_t& r1, uint32_t a) {
    asm volatile("ldmatrix.sync.aligned.m8n8.x2.trans.shared.b16 {%0,%1}, [%2];"
        : "=r"(r0), "=r"(r1) : "r"(a));
}
__device__ __forceinline__ void mma_bf16(float* c, const uint32_t* a, const uint32_t* b) {
    asm volatile("mma.sync.aligned.m16n8k16.row.col.f32.bf16.bf16.f32 "
        "{%0,%1,%2,%3}, {%4,%5,%6,%7}, {%8,%9}, {%0,%1,%2,%3};"
        : "+f"(c[0]), "+f"(c[1]), "+f"(c[2]), "+f"(c[3])
        : "r"(a[0]), "r"(a[1]), "r"(a[2]), "r"(a[3]), "r"(b[0]), "r"(b[1]));
}
__device__ __forceinline__ uint32_t pack_bf16(float a, float b) {
    __nv_bfloat162 h = __nv_bfloat162(__float2bfloat16(a), __float2bfloat16(b));
    return *(uint32_t*)&h;
}

// ---------------------------------------------------------------------------
// split fp32 -> (hi, lo) bf16
// ---------------------------------------------------------------------------
__global__ __launch_bounds__(256)
void split_kernel(const float4* __restrict__ in, __nv_bfloat162* __restrict__ hi,
                  __nv_bfloat162* __restrict__ lo, int n4) {
    int i = blockIdx.x * blockDim.x + threadIdx.x;
    if (i >= n4) return;
    float4 v = in[i];
    __nv_bfloat16 hx = __float2bfloat16(v.x), hy = __float2bfloat16(v.y);
    __nv_bfloat16 hz = __float2bfloat16(v.z), hw = __float2bfloat16(v.w);
    hi[(size_t)i*2]   = __nv_bfloat162(hx, hy);
    hi[(size_t)i*2+1] = __nv_bfloat162(hz, hw);
    lo[(size_t)i*2]   = __nv_bfloat162(__float2bfloat16(v.x - __bfloat162float(hx)),
                                       __float2bfloat16(v.y - __bfloat162float(hy)));
    lo[(size_t)i*2+1] = __nv_bfloat162(__float2bfloat16(v.z - __bfloat162float(hz)),
                                       __float2bfloat16(v.w - __bfloat162float(hw)));
}

// ---------------------------------------------------------------------------
// Warp-MMA split-bf16 NT GEMM. Block 128x128, BK=64, 8 warps (warp 32x64).
// 3-stage cp.async ring (36KB/stage), prefetch distance 2, 1 barrier/chunk.
// B loaded with ldsm_x4 (2 n-blocks per instruction).
// MODE 0: split-store q/k/v hi+lo.  MODE 1: fp32 store to C.
// ---------------------------------------------------------------------------
#define BK      64
#define LDSM_B  144              // 64 bf16 = 128B + 16B pad
#define ASTG    (128*LDSM_B)     // 18432 per operand per stage
#define STAGE2  (2*ASTG)         // 36864 per stage (A+B)

template<int MODE>
__global__ __launch_bounds__(256, 2)
void gemm_mma(const __nv_bfloat16* __restrict__ Ah, const __nv_bfloat16* __restrict__ Al,
              const __nv_bfloat16* __restrict__ Bh, const __nv_bfloat16* __restrict__ Bl,
              const float* __restrict__ bias, float* __restrict__ C, int N)
{
    constexpr int K = DM;
    constexpr int NCHUNK = 3 * (K / BK);   // 48

    extern __shared__ char smem[];
    const uint32_t sb = smem_u32(smem);
    const int tid = threadIdx.x, lane = tid & 31, warp = tid >> 5;
    const int m0 = blockIdx.y * 128, n0 = blockIdx.x * 128;
    const int wm = (warp >> 1) * 32;
    const int wn = (warp & 1) * 64;

    float acc[2][8][4];
#pragma unroll
    for (int mb = 0; mb < 2; mb++)
#pragma unroll
        for (int nb = 0; nb < 8; nb++)
#pragma unroll
            for (int r = 0; r < 4; r++) acc[mb][nb][r] = 0.f;

    // cp.async mapping: per operand 128 rows x 8 x 16B = 1024 chunks, 4 iters
    const int ldr = tid >> 1;                 // 0..127
    const int ldc = tid & 1;                  // 0..1 (which 64B half-pair)

    auto issue_stage = [&](int c, int s) {
        const int seg = c >> 4;               // 16 chunks per segment
        const int kc = (c & 15) * BK;
        const __nv_bfloat16* Ap = (seg == 1) ? Al : Ah;
        const __nv_bfloat16* Bp = (seg == 2) ? Bl : Bh;
        const uint32_t aOff = sb + s * STAGE2;
        const uint32_t bOff = aOff + ASTG;
#pragma unroll
        for (int hh = 0; hh < 4; hh++) {
            int c16 = ldc * 4 + hh;           // 0..7, 16B column group
            uint32_t doff = ldr * LDSM_B + c16 * 16;
            cp_async16(aOff + doff, Ap + (size_t)(m0 + ldr) * K + kc + c16 * 8);
            cp_async16(bOff + doff, Bp + (size_t)(n0 + ldr) * K + kc + c16 * 8);
        }
    };

    issue_stage(0, 0); CP_COMMIT();
    issue_stage(1, 1); CP_COMMIT();

    for (int c = 0; c < NCHUNK; c++) {
        const int s = c % 3;
        if (c + 1 < NCHUNK) CP_WAIT1(); else CP_WAIT0();
        __syncthreads();                      // single barrier per chunk
        if (c + 2 < NCHUNK) { issue_stage(c + 2, (c + 2) % 3); CP_COMMIT(); }

        const uint32_t aBase = sb + s * STAGE2;
        const uint32_t bBase = aBase + ASTG;

#pragma unroll
        for (int ks = 0; ks < 4; ks++) {
            uint32_t afrag[2][4];
#pragma unroll
            for (int mb = 0; mb < 2; mb++) {
                uint32_t addr = aBase + (wm + mb * 16 + (lane & 15)) * LDSM_B
                              + (ks * 16 + (lane >> 4) * 8) * 2;
                ldsm_x4(afrag[mb][0], afrag[mb][1], afrag[mb][2], afrag[mb][3], addr);
            }
#pragma unroll
            for (int nbp = 0; nbp < 4; nbp++) {
                uint32_t r0, r1, r2, r3;
                uint32_t addr = bBase
                              + (wn + nbp * 16 + ((lane >> 4) & 1) * 8 + (lane & 7)) * LDSM_B
                              + (ks * 16 + ((lane >> 3) & 1) * 8) * 2;
                ldsm_x4(r0, r1, r2, r3, addr);
                uint32_t bf0[2] = {r0, r1}, bf1[2] = {r2, r3};
#pragma unroll
                for (int mb = 0; mb < 2; mb++) {
                    mma_bf16(acc[mb][nbp * 2 + 0], afrag[mb], bf0);
                    mma_bf16(acc[mb][nbp * 2 + 1], afrag[mb], bf1);
                }
            }
        }
    }

#pragma unroll
    for (int mb = 0; mb < 2; mb++) {
#pragma unroll
        for (int nb = 0; nb < 8; nb++) {
            int n_g = n0 + wn + nb * 8 + 2 * (lane & 3);
            float bx = bias[n_g], by = bias[n_g + 1];
#pragma unroll
            for (int hh = 0; hh < 2; hh++) {
                int m_g = m0 + wm + mb * 16 + (lane >> 2) + hh * 8;
                float vx = acc[mb][nb][hh * 2 + 0] + bx;
                float vy = acc[mb][nb][hh * 2 + 1] + by;
                if (MODE == 0) {
                    int which = n_g >> 10;
                    int rem = n_g & 1023;
                    int hd = rem & 63, hdh = rem >> 6;
                    int bb = m_g >> 11, ss = m_g & 2047;
                    size_t off = ((size_t)(bb * NHEADS + hdh) * SEQ + ss) * HDIM + hd;
                    __nv_bfloat16 hx = __float2bfloat16(vx), hy = __float2bfloat16(vy);
                    __nv_bfloat162 hi2(hx, hy);
                    __nv_bfloat162 lo2(__float2bfloat16(vx - __bfloat162float(hx)),
                                       __float2bfloat16(vy - __bfloat162float(hy)));
                    __nv_bfloat16 *bh, *bl;
                    if (which == 0)      { bh = g_qh; bl = g_ql; }
                    else if (which == 1) { bh = g_kh; bl = g_kl; }
                    else                 { bh = g_vh; bl = g_vl; }
                    *(__nv_bfloat162*)(bh + off) = hi2;
                    *(__nv_bfloat162*)(bl + off) = lo2;
                } else {
                    *(float2*)(C + (size_t)m_g * N + n_g) = make_float2(vx, vy);
                }
            }
        }
    }
}

// ---------------------------------------------------------------------------
// MMA flash attention, split-bf16 (unchanged from R8)
// ---------------------------------------------------------------------------
#define ALD   144
#define TSZ   (64*ALD)
#define STG4  (4*TSZ)

__global__ __launch_bounds__(256)
void attn_mma()
{
    extern __shared__ char smem[];
    const uint32_t sb = smem_u32(smem);
    const int tid = threadIdx.x, lane = tid & 31, warp = tid >> 5;
    const int qt = 15 - blockIdx.x;
    const int h = blockIdx.y, b = blockIdx.z;
    const int q0 = qt * 128;
    const size_t base = (size_t)(b * NHEADS + h) * SEQ * HDIM;
    const __nv_bfloat16 *qhp = g_qh + base, *qlp = g_ql + base;
    const __nv_bfloat16 *khp = g_kh + base, *klp = g_kl + base;
    const __nv_bfloat16 *vhp = g_vh + base, *vlp = g_vl + base;

    uint32_t qhf[4][4], qlf[4][4];
    for (int half = 0; half < 2; half++) {
        const __nv_bfloat16* src = half ? qlp : qhp;
#pragma unroll
        for (int it = 0; it < 4; it++) {
            int ch = tid + it * 256;
            int row = ch >> 3, c8 = ch & 7;
            cp_async16(sb + row * ALD + c8 * 16, src + (size_t)(q0 + row) * HDIM + c8 * 8);
        }
        CP_COMMIT(); CP_WAIT0();
        __syncthreads();
        uint32_t (*qf)[4] = half ? qlf : qhf;
#pragma unroll
        for (int ks = 0; ks < 4; ks++) {
            uint32_t addr = sb + (warp * 16 + (lane & 15)) * ALD + (ks * 16 + (lane >> 4) * 8) * 2;
            ldsm_x4(qf[ks][0], qf[ks][1], qf[ks][2], qf[ks][3], addr);
        }
        __syncthreads();
    }

    float oacc[8][4];
#pragma unroll
    for (int nb = 0; nb < 8; nb++)
#pragma unroll
        for (int r = 0; r < 4; r++) oacc[nb][r] = 0.f;
    float mrow[2] = {-1e30f, -1e30f}, lrow[2] = {0.f, 0.f};

    const int nkt = 2 * (qt + 1);

    auto issue_kv = [&](int kt, int s) {
        const int k0 = kt * 64;
        const __nv_bfloat16* srcs[4] = {khp, klp, vhp, vlp};
#pragma unroll
        for (int it = 0; it < 8; it++) {
            int ch = tid + it * 256;
            int t = ch >> 9, row = (ch >> 3) & 63, c8 = ch & 7;
            cp_async16(sb + s * STG4 + t * TSZ + row * ALD + c8 * 16,
                       srcs[t] + (size_t)(k0 + row) * HDIM + c8 * 8);
        }
    };

    issue_kv(0, 0); CP_COMMIT();

    for (int kt = 0; kt < nkt; kt++) {
        const int s = kt & 1;
        const int k0 = kt * 64;
        if (kt + 1 < nkt) { issue_kv(kt + 1, s ^ 1); CP_COMMIT(); CP_WAIT1(); }
        else              { CP_WAIT0(); }
        __syncthreads();

        const bool active = (k0 <= q0 + warp * 16 + 15);
        if (active) {
            const uint32_t khB = sb + s * STG4;
            const uint32_t klB = khB + TSZ;
            const uint32_t vhB = khB + 2 * TSZ;
            const uint32_t vlB = khB + 3 * TSZ;

            float sacc[8][4];
#pragma unroll
            for (int nb = 0; nb < 8; nb++)
#pragma unroll
                for (int r = 0; r < 4; r++) sacc[nb][r] = 0.f;

#pragma unroll
            for (int ks = 0; ks < 4; ks++)
#pragma unroll
                for (int nb = 0; nb < 8; nb++) {
                    uint32_t bf[2];
                    uint32_t addr = khB + (nb * 8 + (lane & 7)) * ALD
                                  + (ks * 16 + ((lane >> 3) & 1) * 8) * 2;
                    ldsm_x2(bf[0], bf[1], addr);
                    mma_bf16(sacc[nb], qhf[ks], bf);
                    mma_bf16(sacc[nb], qlf[ks], bf);
                }
#pragma unroll
            for (int ks = 0; ks < 4; ks++)
#pragma unroll
                for (int nb = 0; nb < 8; nb++) {
                    uint32_t bf[2];
                    uint32_t addr = klB + (nb * 8 + (lane & 7)) * ALD
                                  + (ks * 16 + ((lane >> 3) & 1) * 8) * 2;
                    ldsm_x2(bf[0], bf[1], addr);
                    mma_bf16(sacc[nb], qhf[ks], bf);
                }

            const float scale = 0.125f;
            const int gr0 = q0 + warp * 16 + (lane >> 2);
            const bool need_mask = (k0 + 63 > gr0);
#pragma unroll
            for (int nb = 0; nb < 8; nb++) {
                int col = k0 + nb * 8 + (lane & 3) * 2;
#pragma unroll
                for (int e = 0; e < 2; e++) {
                    sacc[nb][e]     = (need_mask && (col + e > gr0))     ? -1e30f : sacc[nb][e] * scale;
                    sacc[nb][e + 2] = (need_mask && (col + e > gr0 + 8)) ? -1e30f : sacc[nb][e + 2] * scale;
                }
            }

            float alpha[2];
#pragma unroll
            for (int r = 0; r < 2; r++) {
                float m = -1e30f;
#pragma unroll
                for (int nb = 0; nb < 8; nb++)
                    m = fmaxf(m, fmaxf(sacc[nb][r * 2], sacc[nb][r * 2 + 1]));
                m = fmaxf(m, __shfl_xor_sync(0xffffffffu, m, 1));
                m = fmaxf(m, __shfl_xor_sync(0xffffffffu, m, 2));
                float mnew = fmaxf(mrow[r], m);
                alpha[r] = __expf(mrow[r] - mnew);
                float rs = 0.f;
#pragma unroll
                for (int nb = 0; nb < 8; nb++) {
                    float p0 = __expf(sacc[nb][r * 2]     - mnew);
                    float p1 = __expf(sacc[nb][r * 2 + 1] - mnew);
                    sacc[nb][r * 2] = p0; sacc[nb][r * 2 + 1] = p1;
                    rs += p0 + p1;
                }
                rs += __shfl_xor_sync(0xffffffffu, rs, 1);
                rs += __shfl_xor_sync(0xffffffffu, rs, 2);
                lrow[r] = lrow[r] * alpha[r] + rs;
                mrow[r] = mnew;
            }
#pragma unroll
            for (int nb = 0; nb < 8; nb++) {
                oacc[nb][0] *= alpha[0]; oacc[nb][1] *= alpha[0];
                oacc[nb][2] *= alpha[1]; oacc[nb][3] *= alpha[1];
            }

            uint32_t phf[4][4], plf[4][4];
#pragma unroll
            for (int j = 0; j < 4; j++) {
#pragma unroll
                for (int q = 0; q < 4; q++) {
                    float a = sacc[2 * j + (q >> 1)][(q & 1) * 2];
                    float bq = sacc[2 * j + (q >> 1)][(q & 1) * 2 + 1];
                    __nv_bfloat16 ha = __float2bfloat16(a), hb = __float2bfloat16(bq);
                    phf[j][q] = pack_bf16(a, bq);
                    plf[j][q] = pack_bf16(a - __bfloat162float(ha), bq - __bfloat162float(hb));
                }
            }

#pragma unroll
            for (int j = 0; j < 4; j++)
#pragma unroll
                for (int nb = 0; nb < 8; nb++) {
                    uint32_t bf[2];
                    uint32_t addr = vhB + (16 * j + (lane & 15)) * ALD + nb * 16;
                    ldsm_x2t(bf[0], bf[1], addr);
                    mma_bf16(oacc[nb], phf[j], bf);
                    mma_bf16(oacc[nb], plf[j], bf);
                }
#pragma unroll
            for (int j = 0; j < 4; j++)
#pragma unroll
                for (int nb = 0; nb < 8; nb++) {
                    uint32_t bf[2];
                    uint32_t addr = vlB + (16 * j + (lane & 15)) * ALD + nb * 16;
                    ldsm_x2t(bf[0], bf[1], addr);
                    mma_bf16(oacc[nb], phf[j], bf);
                }
        }
        __syncthreads();
    }

    float inv[2] = {1.f / lrow[0], 1.f / lrow[1]};
#pragma unroll
    for (int nb = 0; nb < 8; nb++) {
#pragma unroll
        for (int r = 0; r < 2; r++) {
            int gq = q0 + warp * 16 + (lane >> 2) + r * 8;
            float vx = oacc[nb][r * 2] * inv[r];
            float vy = oacc[nb][r * 2 + 1] * inv[r];
            size_t off = (size_t)(b * SEQ + gq) * DM + h * HDIM + nb * 8 + (lane & 3) * 2;
            __nv_bfloat16 hx = __float2bfloat16(vx), hy = __float2bfloat16(vy);
            *(__nv_bfloat162*)(g_ah + off) = __nv_bfloat162(hx, hy);
            *(__nv_bfloat162*)(g_al + off) = __nv_bfloat162(
                __float2bfloat16(vx - __bfloat162float(hx)),
                __float2bfloat16(vy - __bfloat162float(hy)));
        }
    }
}

// ---------------------------------------------------------------------------
extern "C" void kernel_launch(void* const* d_in, const int* in_sizes, int n_in,
                              void* d_out, int out_size)
{
    const float* x     = (const float*)d_in[0];
    const float* qkv_w = (const float*)d_in[1];
    const float* qkv_b = (const float*)d_in[2];
    const float* out_w = (const float*)d_in[3];
    const float* out_b = (const float*)d_in[4];
    float* out = (float*)d_out;

    void *xh, *xl, *wh, *wl, *oh, *ol, *ah, *al;
    cudaGetSymbolAddress(&xh, g_xh); cudaGetSymbolAddress(&xl, g_xl);
    cudaGetSymbolAddress(&wh, g_wh); cudaGetSymbolAddress(&wl, g_wl);
    cudaGetSymbolAddress(&oh, g_oh); cudaGetSymbolAddress(&ol, g_ol);
    cudaGetSymbolAddress(&ah, g_ah); cudaGetSymbolAddress(&al, g_al);

    const int GEMM_SMEM = 3 * STAGE2;   // 110592 (3 stages x A+B)
    const int ATTN_SMEM = 2 * STG4;     // 73728
    cudaFuncSetAttribute(gemm_mma<0>, cudaFuncAttributeMaxDynamicSharedMemorySize, GEMM_SMEM);
    cudaFuncSetAttribute(gemm_mma<1>, cudaFuncAttributeMaxDynamicSharedMemorySize, GEMM_SMEM);
    cudaFuncSetAttribute(attn_mma,    cudaFuncAttributeMaxDynamicSharedMemorySize, ATTN_SMEM);

    split_kernel<<<(MT*DM/4)/256, 256>>>((const float4*)x, (__nv_bfloat162*)xh, (__nv_bfloat162*)xl, MT*DM/4);
    split_kernel<<<(3*DM*DM/4)/256, 256>>>((const float4*)qkv_w, (__nv_bfloat162*)wh, (__nv_bfloat162*)wl, 3*DM*DM/4);
    split_kernel<<<(DM*DM/4)/256, 256>>>((const float4*)out_w, (__nv_bfloat162*)oh, (__nv_bfloat162*)ol, DM*DM/4);

    gemm_mma<0><<<dim3(3*DM/128, MT/128), 256, GEMM_SMEM>>>(
        (const __nv_bfloat16*)xh, (const __nv_bfloat16*)xl,
        (const __nv_bfloat16*)wh, (const __nv_bfloat16*)wl,
        qkv_b, nullptr, 3*DM);

    attn_mma<<<dim3(SEQ/128, NHEADS, BATCH), 256, ATTN_SMEM>>>();

    gemm_mma<1><<<dim3(DM/128, MT/128), 256, GEMM_SMEM>>>(
        (const __nv_bfloat16*)ah, (const __nv_bfloat16*)al,
        (const __nv_bfloat16*)oh, (const __nv_bfloat16*)ol,
        out_b, out, DM);
}

// round 14
// speedup vs baseline: 1.1242x; 1.1242x over previous
#include <cuda_runtime.h>
#include <cuda_bf16.h>
#include <cstdint>

#define NHEADS 16
#define HDIM   64
#define BATCH  2
#define SEQ    2048
#define DM     1024
#define MT     (BATCH*SEQ)   // 4096

// ---------------- scratch (device globals; allocation-free) ----------------
__device__ __nv_bfloat16 g_xh[(size_t)MT*DM],   g_xl[(size_t)MT*DM];
__device__ __nv_bfloat16 g_wh[(size_t)3*DM*DM], g_wl[(size_t)3*DM*DM];
__device__ __nv_bfloat16 g_oh[(size_t)DM*DM],   g_ol[(size_t)DM*DM];
__device__ __nv_bfloat16 g_ah[(size_t)MT*DM],   g_al[(size_t)MT*DM];
__device__ __nv_bfloat16 g_qh[(size_t)BATCH*NHEADS*SEQ*HDIM], g_ql[(size_t)BATCH*NHEADS*SEQ*HDIM];
__device__ __nv_bfloat16 g_kh[(size_t)BATCH*NHEADS*SEQ*HDIM], g_kl[(size_t)BATCH*NHEADS*SEQ*HDIM];
__device__ __nv_bfloat16 g_vh[(size_t)BATCH*NHEADS*SEQ*HDIM], g_vl[(size_t)BATCH*NHEADS*SEQ*HDIM];

// ---------------- helpers ----------------
__device__ __forceinline__ uint32_t smem_u32(const void* p) {
    uint32_t a;
    asm("{ .reg .u64 t; cvta.to.shared.u64 t, %1; cvt.u32.u64 %0, t; }" : "=r"(a) : "l"(p));
    return a;
}
__device__ __forceinline__ void cp_async16(uint32_t dst, const void* src) {
    asm volatile("cp.async.cg.shared.global [%0], [%1], 16;" :: "r"(dst), "l"(src));
}
#define CP_COMMIT()  asm volatile("cp.async.commit_group;" ::: "memory")
#define CP_WAIT1()   asm volatile("cp.async.wait_group 1;" ::: "memory")
#define CP_WAIT0()   asm volatile("cp.async.wait_group 0;" ::: "memory")

__device__ __forceinline__ void ldsm_x4(uint32_t& r0, uint32_t& r1, uint32_t& r2, uint32_t& r3, uint32_t a) {
    asm volatile("ldmatrix.sync.aligned.m8n8.x4.shared.b16 {%0,%1,%2,%3}, [%4];"
        : "=r"(r0), "=r"(r1), "=r"(r2), "=r"(r3) : "r"(a));
}
__device__ __forceinline__ void ldsm_x2(uint32_t& r0, uint32_t& r1, uint32_t a) {
    asm volatile("ldmatrix.sync.aligned.m8n8.x2.shared.b16 {%0,%1}, [%2];"
        : "=r"(r0), "=r"(r1) : "r"(a));
}
__device__ __forceinline__ void ldsm_x2t(uint32_t& r0, uint32_t& r1, uint32_t a) {
    asm volatile("ldmatrix.sync.aligned.m8n8.x2.trans.shared.b16 {%0,%1}, [%2];"
        : "=r"(r0), "=r"(r1) : "r"(a));
}
__device__ __forceinline__ void mma_bf16(float* c, const uint32_t* a, const uint32_t* b) {
    asm volatile("mma.sync.aligned.m16n8k16.row.col.f32.bf16.bf16.f32 "
        "{%0,%1,%2,%3}, {%4,%5,%6,%7}, {%8,%9}, {%0,%1,%2,%3};"
        : "+f"(c[0]), "+f"(c[1]), "+f"(c[2]), "+f"(c[3])
        : "r"(a[0]), "r"(a[1]), "r"(a[2]), "r"(a[3]), "r"(b[0]), "r"(b[1]));
}
__device__ __forceinline__ uint32_t pack_bf16(float a, float b) {
    __nv_bfloat162 h = __nv_bfloat162(__float2bfloat16(a), __float2bfloat16(b));
    return *(uint32_t*)&h;
}

// ---------------------------------------------------------------------------
// split fp32 -> (hi, lo) bf16
// ---------------------------------------------------------------------------
__global__ __launch_bounds__(256)
void split_kernel(const float4* __restrict__ in, __nv_bfloat162* __restrict__ hi,
                  __nv_bfloat162* __restrict__ lo, int n4) {
    int i = blockIdx.x * blockDim.x + threadIdx.x;
    if (i >= n4) return;
    float4 v = in[i];
    __nv_bfloat16 hx = __float2bfloat16(v.x), hy = __float2bfloat16(v.y);
    __nv_bfloat16 hz = __float2bfloat16(v.z), hw = __float2bfloat16(v.w);
    hi[(size_t)i*2]   = __nv_bfloat162(hx, hy);
    hi[(size_t)i*2+1] = __nv_bfloat162(hz, hw);
    lo[(size_t)i*2]   = __nv_bfloat162(__float2bfloat16(v.x - __bfloat162float(hx)),
                                       __float2bfloat16(v.y - __bfloat162float(hy)));
    lo[(size_t)i*2+1] = __nv_bfloat162(__float2bfloat16(v.z - __bfloat162float(hz)),
                                       __float2bfloat16(v.w - __bfloat162float(hw)));
}

// ---------------------------------------------------------------------------
// Warp-MMA split-bf16 NT GEMM. Block 128x128, BK=64, **16 warps, warp 32x32**.
// 512 threads, <=64 regs (launch_bounds 512,2) -> 32 warps/SM (occ 50%).
// 3-stage cp.async ring, prefetch distance 2, 1 barrier/chunk.
// MODE 0: split-store q/k/v hi+lo.  MODE 1: fp32 store to C.
// ---------------------------------------------------------------------------
#define BK      64
#define LDSM_B  144              // 64 bf16 = 128B + 16B pad
#define ASTG    (128*LDSM_B)     // 18432 per operand per stage
#define STAGE2  (2*ASTG)         // 36864 per stage (A+B)

template<int MODE>
__global__ __launch_bounds__(512, 2)
void gemm_mma(const __nv_bfloat16* __restrict__ Ah, const __nv_bfloat16* __restrict__ Al,
              const __nv_bfloat16* __restrict__ Bh, const __nv_bfloat16* __restrict__ Bl,
              const float* __restrict__ bias, float* __restrict__ C, int N)
{
    constexpr int K = DM;
    constexpr int NCHUNK = 3 * (K / BK);   // 48

    extern __shared__ char smem[];
    const uint32_t sb = smem_u32(smem);
    const int tid = threadIdx.x, lane = tid & 31, warp = tid >> 5;
    const int m0 = blockIdx.y * 128, n0 = blockIdx.x * 128;
    const int wm = (warp & 3) * 32;       // 4 m-slices
    const int wn = (warp >> 2) * 32;      // 4 n-slices

    float acc[2][4][4];
#pragma unroll
    for (int mb = 0; mb < 2; mb++)
#pragma unroll
        for (int nb = 0; nb < 4; nb++)
#pragma unroll
            for (int r = 0; r < 4; r++) acc[mb][nb][r] = 0.f;

    // cp.async mapping: per operand 128 rows x 8 x 16B = 1024 chunks; 512 thr x 2
    const int ldr = tid >> 2;             // 0..127
    const int ldq = tid & 3;              // 0..3

    auto issue_stage = [&](int c, int s) {
        const int seg = c >> 4;
        const int kc = (c & 15) * BK;
        const __nv_bfloat16* Ap = (seg == 1) ? Al : Ah;
        const __nv_bfloat16* Bp = (seg == 2) ? Bl : Bh;
        const uint32_t aOff = sb + s * STAGE2;
        const uint32_t bOff = aOff + ASTG;
#pragma unroll
        for (int hh = 0; hh < 2; hh++) {
            int c16 = ldq * 2 + hh;       // 0..7
            uint32_t doff = ldr * LDSM_B + c16 * 16;
            cp_async16(aOff + doff, Ap + (size_t)(m0 + ldr) * K + kc + c16 * 8);
            cp_async16(bOff + doff, Bp + (size_t)(n0 + ldr) * K + kc + c16 * 8);
        }
    };

    issue_stage(0, 0); CP_COMMIT();
    issue_stage(1, 1); CP_COMMIT();

    for (int c = 0; c < NCHUNK; c++) {
        const int s = c % 3;
        if (c + 1 < NCHUNK) CP_WAIT1(); else CP_WAIT0();
        __syncthreads();                  // single barrier per chunk
        if (c + 2 < NCHUNK) { issue_stage(c + 2, (c + 2) % 3); CP_COMMIT(); }

        const uint32_t aBase = sb + s * STAGE2;
        const uint32_t bBase = aBase + ASTG;

#pragma unroll
        for (int ks = 0; ks < 4; ks++) {
            uint32_t afrag[2][4];
#pragma unroll
            for (int mb = 0; mb < 2; mb++) {
                uint32_t addr = aBase + (wm + mb * 16 + (lane & 15)) * LDSM_B
                              + (ks * 16 + (lane >> 4) * 8) * 2;
                ldsm_x4(afrag[mb][0], afrag[mb][1], afrag[mb][2], afrag[mb][3], addr);
            }
#pragma unroll
            for (int nbp = 0; nbp < 2; nbp++) {
                uint32_t r0, r1, r2, r3;
                uint32_t addr = bBase
                              + (wn + nbp * 16 + ((lane >> 4) & 1) * 8 + (lane & 7)) * LDSM_B
                              + (ks * 16 + ((lane >> 3) & 1) * 8) * 2;
                ldsm_x4(r0, r1, r2, r3, addr);
                uint32_t bf0[2] = {r0, r1}, bf1[2] = {r2, r3};
#pragma unroll
                for (int mb = 0; mb < 2; mb++) {
                    mma_bf16(acc[mb][nbp * 2 + 0], afrag[mb], bf0);
                    mma_bf16(acc[mb][nbp * 2 + 1], afrag[mb], bf1);
                }
            }
        }
    }

#pragma unroll
    for (int mb = 0; mb < 2; mb++) {
#pragma unroll
        for (int nb = 0; nb < 4; nb++) {
            int n_g = n0 + wn + nb * 8 + 2 * (lane & 3);
            float bx = bias[n_g], by = bias[n_g + 1];
#pragma unroll
            for (int hh = 0; hh < 2; hh++) {
                int m_g = m0 + wm + mb * 16 + (lane >> 2) + hh * 8;
                float vx = acc[mb][nb][hh * 2 + 0] + bx;
                float vy = acc[mb][nb][hh * 2 + 1] + by;
                if (MODE == 0) {
                    int which = n_g >> 10;
                    int rem = n_g & 1023;
                    int hd = rem & 63, hdh = rem >> 6;
                    int bb = m_g >> 11, ss = m_g & 2047;
                    size_t off = ((size_t)(bb * NHEADS + hdh) * SEQ + ss) * HDIM + hd;
                    __nv_bfloat16 hx = __float2bfloat16(vx), hy = __float2bfloat16(vy);
                    __nv_bfloat162 hi2(hx, hy);
                    __nv_bfloat162 lo2(__float2bfloat16(vx - __bfloat162float(hx)),
                                       __float2bfloat16(vy - __bfloat162float(hy)));
                    __nv_bfloat16 *bh, *bl;
                    if (which == 0)      { bh = g_qh; bl = g_ql; }
                    else if (which == 1) { bh = g_kh; bl = g_kl; }
                    else                 { bh = g_vh; bl = g_vl; }
                    *(__nv_bfloat162*)(bh + off) = hi2;
                    *(__nv_bfloat162*)(bl + off) = lo2;
                } else {
                    *(float2*)(C + (size_t)m_g * N + n_g) = make_float2(vx, vy);
                }
            }
        }
    }
}

// ---------------------------------------------------------------------------
// MMA flash attention, split-bf16 (unchanged from R8)
// ---------------------------------------------------------------------------
#define ALD   144
#define TSZ   (64*ALD)
#define STG4  (4*TSZ)

__global__ __launch_bounds__(256)
void attn_mma()
{
    extern __shared__ char smem[];
    const uint32_t sb = smem_u32(smem);
    const int tid = threadIdx.x, lane = tid & 31, warp = tid >> 5;
    const int qt = 15 - blockIdx.x;
    const int h = blockIdx.y, b = blockIdx.z;
    const int q0 = qt * 128;
    const size_t base = (size_t)(b * NHEADS + h) * SEQ * HDIM;
    const __nv_bfloat16 *qhp = g_qh + base, *qlp = g_ql + base;
    const __nv_bfloat16 *khp = g_kh + base, *klp = g_kl + base;
    const __nv_bfloat16 *vhp = g_vh + base, *vlp = g_vl + base;

    uint32_t qhf[4][4], qlf[4][4];
    for (int half = 0; half < 2; half++) {
        const __nv_bfloat16* src = half ? qlp : qhp;
#pragma unroll
        for (int it = 0; it < 4; it++) {
            int ch = tid + it * 256;
            int row = ch >> 3, c8 = ch & 7;
            cp_async16(sb + row * ALD + c8 * 16, src + (size_t)(q0 + row) * HDIM + c8 * 8);
        }
        CP_COMMIT(); CP_WAIT0();
        __syncthreads();
        uint32_t (*qf)[4] = half ? qlf : qhf;
#pragma unroll
        for (int ks = 0; ks < 4; ks++) {
            uint32_t addr = sb + (warp * 16 + (lane & 15)) * ALD + (ks * 16 + (lane >> 4) * 8) * 2;
            ldsm_x4(qf[ks][0], qf[ks][1], qf[ks][2], qf[ks][3], addr);
        }
        __syncthreads();
    }

    float oacc[8][4];
#pragma unroll
    for (int nb = 0; nb < 8; nb++)
#pragma unroll
        for (int r = 0; r < 4; r++) oacc[nb][r] = 0.f;
    float mrow[2] = {-1e30f, -1e30f}, lrow[2] = {0.f, 0.f};

    const int nkt = 2 * (qt + 1);

    auto issue_kv = [&](int kt, int s) {
        const int k0 = kt * 64;
        const __nv_bfloat16* srcs[4] = {khp, klp, vhp, vlp};
#pragma unroll
        for (int it = 0; it < 8; it++) {
            int ch = tid + it * 256;
            int t = ch >> 9, row = (ch >> 3) & 63, c8 = ch & 7;
            cp_async16(sb + s * STG4 + t * TSZ + row * ALD + c8 * 16,
                       srcs[t] + (size_t)(k0 + row) * HDIM + c8 * 8);
        }
    };

    issue_kv(0, 0); CP_COMMIT();

    for (int kt = 0; kt < nkt; kt++) {
        const int s = kt & 1;
        const int k0 = kt * 64;
        if (kt + 1 < nkt) { issue_kv(kt + 1, s ^ 1); CP_COMMIT(); CP_WAIT1(); }
        else              { CP_WAIT0(); }
        __syncthreads();

        const bool active = (k0 <= q0 + warp * 16 + 15);
        if (active) {
            const uint32_t khB = sb + s * STG4;
            const uint32_t klB = khB + TSZ;
            const uint32_t vhB = khB + 2 * TSZ;
            const uint32_t vlB = khB + 3 * TSZ;

            float sacc[8][4];
#pragma unroll
            for (int nb = 0; nb < 8; nb++)
#pragma unroll
                for (int r = 0; r < 4; r++) sacc[nb][r] = 0.f;

#pragma unroll
            for (int ks = 0; ks < 4; ks++)
#pragma unroll
                for (int nb = 0; nb < 8; nb++) {
                    uint32_t bf[2];
                    uint32_t addr = khB + (nb * 8 + (lane & 7)) * ALD
                                  + (ks * 16 + ((lane >> 3) & 1) * 8) * 2;
                    ldsm_x2(bf[0], bf[1], addr);
                    mma_bf16(sacc[nb], qhf[ks], bf);
                    mma_bf16(sacc[nb], qlf[ks], bf);
                }
#pragma unroll
            for (int ks = 0; ks < 4; ks++)
#pragma unroll
                for (int nb = 0; nb < 8; nb++) {
                    uint32_t bf[2];
                    uint32_t addr = klB + (nb * 8 + (lane & 7)) * ALD
                                  + (ks * 16 + ((lane >> 3) & 1) * 8) * 2;
                    ldsm_x2(bf[0], bf[1], addr);
                    mma_bf16(sacc[nb], qhf[ks], bf);
                }

            const float scale = 0.125f;
            const int gr0 = q0 + warp * 16 + (lane >> 2);
            const bool need_mask = (k0 + 63 > gr0);
#pragma unroll
            for (int nb = 0; nb < 8; nb++) {
                int col = k0 + nb * 8 + (lane & 3) * 2;
#pragma unroll
                for (int e = 0; e < 2; e++) {
                    sacc[nb][e]     = (need_mask && (col + e > gr0))     ? -1e30f : sacc[nb][e] * scale;
                    sacc[nb][e + 2] = (need_mask && (col + e > gr0 + 8)) ? -1e30f : sacc[nb][e + 2] * scale;
                }
            }

            float alpha[2];
#pragma unroll
            for (int r = 0; r < 2; r++) {
                float m = -1e30f;
#pragma unroll
                for (int nb = 0; nb < 8; nb++)
                    m = fmaxf(m, fmaxf(sacc[nb][r * 2], sacc[nb][r * 2 + 1]));
                m = fmaxf(m, __shfl_xor_sync(0xffffffffu, m, 1));
                m = fmaxf(m, __shfl_xor_sync(0xffffffffu, m, 2));
                float mnew = fmaxf(mrow[r], m);
                alpha[r] = __expf(mrow[r] - mnew);
                float rs = 0.f;
#pragma unroll
                for (int nb = 0; nb < 8; nb++) {
                    float p0 = __expf(sacc[nb][r * 2]     - mnew);
                    float p1 = __expf(sacc[nb][r * 2 + 1] - mnew);
                    sacc[nb][r * 2] = p0; sacc[nb][r * 2 + 1] = p1;
                    rs += p0 + p1;
                }
                rs += __shfl_xor_sync(0xffffffffu, rs, 1);
                rs += __shfl_xor_sync(0xffffffffu, rs, 2);
                lrow[r] = lrow[r] * alpha[r] + rs;
                mrow[r] = mnew;
            }
#pragma unroll
            for (int nb = 0; nb < 8; nb++) {
                oacc[nb][0] *= alpha[0]; oacc[nb][1] *= alpha[0];
                oacc[nb][2] *= alpha[1]; oacc[nb][3] *= alpha[1];
            }

            uint32_t phf[4][4], plf[4][4];
#pragma unroll
            for (int j = 0; j < 4; j++) {
#pragma unroll
                for (int q = 0; q < 4; q++) {
                    float a = sacc[2 * j + (q >> 1)][(q & 1) * 2];
                    float bq = sacc[2 * j + (q >> 1)][(q & 1) * 2 + 1];
                    __nv_bfloat16 ha = __float2bfloat16(a), hb = __float2bfloat16(bq);
                    phf[j][q] = pack_bf16(a, bq);
                    plf[j][q] = pack_bf16(a - __bfloat162float(ha), bq - __bfloat162float(hb));
                }
            }

#pragma unroll
            for (int j = 0; j < 4; j++)
#pragma unroll
                for (int nb = 0; nb < 8; nb++) {
                    uint32_t bf[2];
                    uint32_t addr = vhB + (16 * j + (lane & 15)) * ALD + nb * 16;
                    ldsm_x2t(bf[0], bf[1], addr);
                    mma_bf16(oacc[nb], phf[j], bf);
                    mma_bf16(oacc[nb], plf[j], bf);
                }
#pragma unroll
            for (int j = 0; j < 4; j++)
#pragma unroll
                for (int nb = 0; nb < 8; nb++) {
                    uint32_t bf[2];
                    uint32_t addr = vlB + (16 * j + (lane & 15)) * ALD + nb * 16;
                    ldsm_x2t(bf[0], bf[1], addr);
                    mma_bf16(oacc[nb], phf[j], bf);
                }
        }
        __syncthreads();
    }

    float inv[2] = {1.f / lrow[0], 1.f / lrow[1]};
#pragma unroll
    for (int nb = 0; nb < 8; nb++) {
#pragma unroll
        for (int r = 0; r < 2; r++) {
            int gq = q0 + warp * 16 + (lane >> 2) + r * 8;
            float vx = oacc[nb][r * 2] * inv[r];
            float vy = oacc[nb][r * 2 + 1] * inv[r];
            size_t off = (size_t)(b * SEQ + gq) * DM + h * HDIM + nb * 8 + (lane & 3) * 2;
            __nv_bfloat16 hx = __float2bfloat16(vx), hy = __float2bfloat16(vy);
            *(__nv_bfloat162*)(g_ah + off) = __nv_bfloat162(hx, hy);
            *(__nv_bfloat162*)(g_al + off) = __nv_bfloat162(
                __float2bfloat16(vx - __bfloat162float(hx)),
                __float2bfloat16(vy - __bfloat162float(hy)));
        }
    }
}

// ---------------------------------------------------------------------------
extern "C" void kernel_launch(void* const* d_in, const int* in_sizes, int n_in,
                              void* d_out, int out_size)
{
    const float* x     = (const float*)d_in[0];
    const float* qkv_w = (const float*)d_in[1];
    const float* qkv_b = (const float*)d_in[2];
    const float* out_w = (const float*)d_in[3];
    const float* out_b = (const float*)d_in[4];
    float* out = (float*)d_out;

    void *xh, *xl, *wh, *wl, *oh, *ol, *ah, *al;
    cudaGetSymbolAddress(&xh, g_xh); cudaGetSymbolAddress(&xl, g_xl);
    cudaGetSymbolAddress(&wh, g_wh); cudaGetSymbolAddress(&wl, g_wl);
    cudaGetSymbolAddress(&oh, g_oh); cudaGetSymbolAddress(&ol, g_ol);
    cudaGetSymbolAddress(&ah, g_ah); cudaGetSymbolAddress(&al, g_al);

    const int GEMM_SMEM = 3 * STAGE2;   // 110592 (3 stages x A+B)
    const int ATTN_SMEM = 2 * STG4;     // 73728
    cudaFuncSetAttribute(gemm_mma<0>, cudaFuncAttributeMaxDynamicSharedMemorySize, GEMM_SMEM);
    cudaFuncSetAttribute(gemm_mma<1>, cudaFuncAttributeMaxDynamicSharedMemorySize, GEMM_SMEM);
    cudaFuncSetAttribute(attn_mma,    cudaFuncAttributeMaxDynamicSharedMemorySize, ATTN_SMEM);

    split_kernel<<<(MT*DM/4)/256, 256>>>((const float4*)x, (__nv_bfloat162*)xh, (__nv_bfloat162*)xl, MT*DM/4);
    split_kernel<<<(3*DM*DM/4)/256, 256>>>((const float4*)qkv_w, (__nv_bfloat162*)wh, (__nv_bfloat162*)wl, 3*DM*DM/4);
    split_kernel<<<(DM*DM/4)/256, 256>>>((const float4*)out_w, (__nv_bfloat162*)oh, (__nv_bfloat162*)ol, DM*DM/4);

    gemm_mma<0><<<dim3(3*DM/128, MT/128), 512, GEMM_SMEM>>>(
        (const __nv_bfloat16*)xh, (const __nv_bfloat16*)xl,
        (const __nv_bfloat16*)wh, (const __nv_bfloat16*)wl,
        qkv_b, nullptr, 3*DM);

    attn_mma<<<dim3(SEQ/128, NHEADS, BATCH), 256, ATTN_SMEM>>>();

    gemm_mma<1><<<dim3(DM/128, MT/128), 512, GEMM_SMEM>>>(
        (const __nv_bfloat16*)ah, (const __nv_bfloat16*)al,
        (const __nv_bfloat16*)oh, (const __nv_bfloat16*)ol,
        out_b, out, DM);
}